// round 17
// baseline (speedup 1.0000x reference)
#include <cuda_runtime.h>
#include <cstdint>

// CTC loss, probability-domain forward DP, per-lane block-float exponents.
// R17 = R15 (best: 25.1us, pinned at the ~5.6 TB/s multi-stream DRAM ceiling)
// with an .L2::256B prefetch-granule hint on every cp.async. The warp consumes
// the full 512B row, so 256B-granule prefetch wastes nothing and lets DRAM
// see fewer, larger requests. Everything else byte-identical to R15.
// B=512, T=512, C=128, L=64, S=129, blank=127. One warp per batch element.

#define CTC_B 512
#define CTC_T 512
#define CTC_C 128
#define CTC_L 64
#define CH    8                 // rows per chunk = rescale period
#define RCH   8                 // ring slots (32 KB smem)
#define WA    6                 // write-ahead distance (chunks)
#define NCH   (CTC_T / CH)      // 64 chunks

__global__ __launch_bounds__(32) void ctc_kernel(
    const int* __restrict__ y_true,
    const float* __restrict__ y_pred,
    float* __restrict__ out)
{
    __shared__ float ring[RCH * CH * CTC_C];   // 32 KB

    const float EPS = 1e-7f;
    const unsigned FULL = 0xffffffffu;
    const int b    = blockIdx.x;
    const int lane = threadIdx.x;

    // labels for odd states s=4l+1 (label 2l) and s=4l+3 (label 2l+1)
    const int* lrow = y_true + b * CTC_L;
    const int lab1 = lrow[2 * lane];
    const int lab3 = lrow[2 * lane + 1];
    const int prev1 = (lane > 0) ? lrow[2 * lane - 1] : -1;
    const float m1 = ((lane > 0) && (lab1 != prev1)) ? 1.0f : 0.0f; // skip into 4l+1
    const float m3 = (lab3 != lab1) ? 1.0f : 0.0f;                  // skip into 4l+3

    const float* base = y_pred + (size_t)b * CTC_T * CTC_C;
    const unsigned smb = (unsigned)__cvta_generic_to_shared(ring);
    const unsigned lane4 = 4u * lane;

    // Issue one chunk into slot c&7: 8 rows, 1 cp.async.cg 16B per lane per
    // row (with 256B L2 prefetch granule), 1 commit.
    auto issue_chunk = [&](int c) {
        const unsigned sbase = (unsigned)(c & (RCH - 1)) * (CH * CTC_C);
#pragma unroll
        for (int r = 0; r < CH; ++r) {
            const float* src = base + (size_t)(c * CH + r) * CTC_C + lane4;
            const unsigned dst = smb + (sbase + (unsigned)r * CTC_C + lane4) * 4u;
            asm volatile("cp.async.cg.shared.global.L2::256B [%0], [%1], 16;"
                         :: "r"(dst), "l"(src));
        }
        asm volatile("cp.async.commit_group;");
    };

    // Prologue: fill WA chunks (slots 0..5).
#pragma unroll
    for (int c = 0; c < WA; ++c) issue_chunk(c);

    // virtual pre-init: a0=1 on lane 0 makes step t=0 yield the reference init
    float a0 = (lane == 0) ? 1.0f : 0.0f;
    float a1 = 0.0f, a2 = 0.0f, a3 = 0.0f, a4 = 0.0f;
    int   E  = 0;                            // alpha = a * 2^E (per lane)
    float f  = (lane == 0) ? 0.0f : 1.0f;    // neighbor re-basing factor

    // Process one chunk: 24 LDS gathers + 8 DP steps + rescale (R6-exact).
    auto do_chunk = [&](int c) {
        const int cb = (c & (RCH - 1)) * (CH * CTC_C);
        float pb[CH], p1[CH], p3[CH];
#pragma unroll
        for (int j = 0; j < CH; ++j) {
            const int rb = cb + j * CTC_C;
            pb[j] = ring[rb + (CTC_C - 1)] + EPS;   // blank: broadcast LDS
            p1[j] = ring[rb + lab1] + EPS;
            p3[j] = ring[rb + lab3] + EPS;
        }
#pragma unroll
        for (int j = 0; j < CH; ++j) {
            const float am1 = __shfl_up_sync(FULL, a3, 1) * f;   // lane0: f=0

            const float n0 = (a0 + am1) * pb[j];                 // s=4l (blank)
            const float n1 = fmaf(am1, m1, a1 + a0) * p1[j];     // s=4l+1
            const float n2 = (a2 + a1) * pb[j];                  // s=4l+2 (blank)
            const float n3 = fmaf(a1, m3, a3 + a2) * p3[j];      // s=4l+3
            const float n4 = (a4 + a3) * pb[j];                  // s=128 (lane31)
            a0 = n0; a1 = n1; a2 = n2; a3 = n3; a4 = n4;
        }
        // ---- per-lane power-of-2 rescale (exact R6 logic) ----
        float lm = fmaxf(fmaxf(a0, a1), fmaxf(a2, a3));
        lm = fmaxf(lm, a4);
        int e = (int)(__float_as_uint(lm) >> 23) - 127;
        const bool zero = (lm == 0.0f);
        if (zero) e = 0;
        const float sc = __uint_as_float((unsigned)(127 - e) << 23); // 2^-e
        a0 *= sc; a1 *= sc; a2 *= sc; a3 *= sc; a4 *= sc;
        E += e;
        // all-zero lanes (ahead of the DP wavefront) adopt neighbor's frame
        const int Ep = __shfl_up_sync(FULL, E, 1);
        if (zero && lane > 0) E = Ep;
        // neighbor re-basing factor for the next chunk
        const int Ep2 = __shfl_up_sync(FULL, E, 1);
        int d = Ep2 - E;
        d = max(-126, min(126, d));
        f = __uint_as_float((unsigned)(127 + d) << 23);  // 2^d
        if (lane == 0) f = 0.0f;
    };

    for (int c = 0; c < NCH; c += 2) {
        // Issue chunks c+6, c+7 into slots (c-2)&7, (c-1)&7 — both were read
        // in iteration c-2/c-1 (register-consumed before these issues).
        if (c + WA < NCH) issue_chunk(c + WA);
        else asm volatile("cp.async.commit_group;");
        if (c + WA + 1 < NCH) issue_chunk(c + WA + 1);
        else asm volatile("cp.async.commit_group;");

        // committed = c+8 groups; pending <= 6 -> chunks 0..c+1 complete
        asm volatile("cp.async.wait_group %0;" :: "n"(WA));
        __syncwarp();

        do_chunk(c);
        do_chunk(c + 1);
    }

    if (lane == 31) {
        // P_total = alpha_{T-1}[S-1] + alpha_{T-1}[S-2] = (a4 + a3) * 2^E
        const float p = a4 + a3;
        out[b] = -(__logf(p) + (float)E * 0.69314718055994530942f);
    }
}

extern "C" void kernel_launch(void* const* d_in, const int* in_sizes, int n_in,
                              void* d_out, int out_size) {
    const int*   y_true = (const int*)d_in[0];
    const float* y_pred = (const float*)d_in[1];
    float*       outp   = (float*)d_out;
    (void)in_sizes; (void)n_in; (void)out_size;

    ctc_kernel<<<CTC_B, 32>>>(y_true, y_pred, outp);
}